// round 14
// baseline (speedup 1.0000x reference)
#include <cuda_runtime.h>
#include <cuda_bf16.h>
#include <math.h>
#include <stdint.h>

#define HW 1024
#define CC 1024
#define CR 64

__device__ __forceinline__ float fsigmoid(float v) {
    return __fdividef(1.f, 1.f + __expf(-v));
}

// ---------------- scratch ----------------
__device__ float g_A[32 * 32];
__device__ float g_mean[CC];
__device__ float g_scale[CC];
__device__ float g_xrp[HW * CC];                // sigmoid(x_se), pixel-major [p][c]
__device__ __nv_bfloat16 g_Wh[1024 * 2048];     // conv weight hi/lo bf16 split
__device__ __nv_bfloat16 g_Wl[1024 * 2048];
__device__ __nv_bfloat16 g_Bh[HW * 2048];       // GEMM B hi/lo, K-major [p][k]
__device__ __nv_bfloat16 g_Bl[HW * 2048];

// ---------------- split helper ----------------
__device__ __forceinline__ void bsplit(float v, __nv_bfloat16& h, __nv_bfloat16& l) {
    h = __float2bfloat16(v);
    l = __float2bfloat16(v - __bfloat162float(h));
}

// ---------------- fused prep: convW split | per-channel mean | gaussian table ------
__global__ void k_prep(const float* __restrict__ w, const float* __restrict__ x) {
    int b = blockIdx.x;
    int t = threadIdx.x;   // 256
    if (b < 1024) {
        int base = (b * 256 + t) * 8;
        float4 v0 = *(const float4*)(w + base);
        float4 v1 = *(const float4*)(w + base + 4);
        __nv_bfloat16 h[8], l[8];
        float vv[8] = {v0.x, v0.y, v0.z, v0.w, v1.x, v1.y, v1.z, v1.w};
        #pragma unroll
        for (int i = 0; i < 8; i++) bsplit(vv[i], h[i], l[i]);
        *(uint4*)(g_Wh + base) = *(uint4*)h;
        *(uint4*)(g_Wl + base) = *(uint4*)l;
    } else if (b < 2048) {
        int c = b - 1024;
        const float* xc = x + c * HW;
        float s = 0.f;
        #pragma unroll
        for (int q = 0; q < 4; q++) s += xc[t + q * 256];
        #pragma unroll
        for (int o = 16; o > 0; o >>= 1) s += __shfl_xor_sync(0xffffffffu, s, o);
        __shared__ float red[8];
        int lane = t & 31, wv = t >> 5;
        if (lane == 0) red[wv] = s;
        __syncthreads();
        if (t == 0) {
            float tt = 0.f;
            #pragma unroll
            for (int i = 0; i < 8; i++) tt += red[i];
            g_mean[c] = tt * (1.0f / 1024.0f);
        }
    } else {
        // 1D gaussian table, row-normalized
        int i = t >> 3;
        int x0 = (t & 7) * 4;
        float e[4], s = 0.f;
        #pragma unroll
        for (int q = 0; q < 4; q++) {
            float d = (float)(i - (x0 + q));
            e[q] = __expf(-d * d / 4.5f);
            s += e[q];
        }
        s += __shfl_xor_sync(0xffffffffu, s, 1);
        s += __shfl_xor_sync(0xffffffffu, s, 2);
        s += __shfl_xor_sync(0xffffffffu, s, 4);
        float inv = __fdividef(1.f, s);
        #pragma unroll
        for (int q = 0; q < 4; q++) g_A[i * 32 + x0 + q] = e[q] * inv;
    }
}

// ---------------- fused SE: scale = sigmoid(W2 relu(W1 mean + b1) + b2) ------------
__global__ void k_se(const float* __restrict__ w1, const float* __restrict__ b1,
                     const float* __restrict__ w2, const float* __restrict__ b2) {
    __shared__ float ym[CC];
    __shared__ float h1s[CR];
    int t = threadIdx.x;   // 256
    int w = t >> 5, lane = t & 31;
    #pragma unroll
    for (int q = 0; q < 4; q++) ym[t + q * 256] = g_mean[t + q * 256];
    __syncthreads();
    #pragma unroll
    for (int jj = 0; jj < 8; jj++) {
        int j = w * 8 + jj;
        const float* wr = w1 + j * CC;
        float s = 0.f;
        #pragma unroll
        for (int k = 0; k < 32; k++) s += wr[lane + k * 32] * ym[lane + k * 32];
        #pragma unroll
        for (int o = 16; o > 0; o >>= 1) s += __shfl_xor_sync(0xffffffffu, s, o);
        if (lane == 0) h1s[j] = fmaxf(s + b1[j], 0.f);
    }
    __syncthreads();
    int gid = blockIdx.x * 256 + t;
    int c = gid >> 3, l8 = gid & 7;
    const float* wr = w2 + c * CR;
    float s = 0.f;
    #pragma unroll
    for (int k = 0; k < 8; k++) s += wr[l8 + k * 8] * h1s[l8 + k * 8];
    s += __shfl_xor_sync(0xffffffffu, s, 1);
    s += __shfl_xor_sync(0xffffffffu, s, 2);
    s += __shfl_xor_sync(0xffffffffu, s, 4);
    if (l8 == 0) g_scale[c] = fsigmoid(s + b2[c]);
}

// ---------------- fused channel stage: 8 channels/block, 128 blocks, 512 threads ---
__global__ void __launch_bounds__(512)
k_chan8(const float* __restrict__ x) {
    __shared__ float xs[8][1024];
    __shared__ float At[32][36];    // At[y][k] = A[k][y]
    __shared__ float tm[32][36];
    int c0 = blockIdx.x * 8;
    int t = threadIdx.x;            // 512

    if (t < 256) {
        #pragma unroll
        for (int q = 0; q < 4; q++) {
            int i = t + q * 256;    // i = k*32 + y
            At[i & 31][i >> 5] = g_A[i];
        }
    }
    #pragma unroll
    for (int i = 0; i < 8; i++) {
        float sc = g_scale[c0 + i];
        #pragma unroll
        for (int q = 0; q < 2; q++) {
            int p = t + q * 512;
            xs[i][p] = x[(c0 + i) * HW + p] * sc;
        }
    }
    __syncthreads();

    #pragma unroll
    for (int q = 0; q < 2; q++) {
        int p = t + q * 512;
        float v[8];
        #pragma unroll
        for (int i = 0; i < 8; i++) v[i] = fsigmoid(xs[i][p]);
        *(float4*)(g_xrp + p * CC + c0)     = make_float4(v[0], v[1], v[2], v[3]);
        *(float4*)(g_xrp + p * CC + c0 + 4) = make_float4(v[4], v[5], v[6], v[7]);
    }

    int xrow = t >> 4, k2 = (t & 15) * 2;
    #pragma unroll
    for (int i = 0; i < 8; i++) {
        float a0 = 0.f, a1 = 0.f;
        #pragma unroll
        for (int y = 0; y < 32; y++) {
            float xv = xs[i][xrow * 32 + y];
            a0 += xv * At[y][k2];
            a1 += xv * At[y][k2 + 1];
        }
        __syncthreads();
        tm[xrow][k2] = a0;
        tm[xrow][k2 + 1] = a1;
        __syncthreads();
        float o0 = 0.f, o1 = 0.f;
        #pragma unroll
        for (int xx = 0; xx < 32; xx++) {
            float av = At[xx][xrow];
            o0 += av * tm[xx][k2];
            o1 += av * tm[xx][k2 + 1];
        }
        __syncthreads();
        xs[i][xrow * 32 + k2] = o0;
        xs[i][xrow * 32 + k2 + 1] = o1;
    }
    __syncthreads();

    #pragma unroll
    for (int q = 0; q < 2; q++) {
        int p = t + q * 512;
        __nv_bfloat16 h[8], l[8];
        #pragma unroll
        for (int i = 0; i < 8; i++) bsplit(xs[i][p], h[i], l[i]);
        *(uint4*)(g_Bh + p * 2048 + 1024 + c0) = *(uint4*)h;
        *(uint4*)(g_Bl + p * 2048 + 1024 + c0) = *(uint4*)l;
    }
}

// ---------------- scrambled 3x3 softmax attention -> Bh/Bl (k<1024) ----------------
// snF[F] = neighbor_row[F%9][F/9] (stride-9 scatter fill, conflict-free). Linear
// addressing in hot loops + register cache sv[][] so pass 2 does zero LDS.
__global__ void k_attn() {
    __shared__ float snF[9216];     // [c*9 + kidx]
    __shared__ float wsum[8][9];
    __shared__ float lg[9];
    __shared__ float attn[9];
    int p = blockIdx.x;
    int py = p >> 5, px = p & 31;
    int t = threadIdx.x;  // 256

    #pragma unroll
    for (int kidx = 0; kidx < 9; kidx++) {
        int sy = py + kidx / 3 - 1;
        int sx = px + kidx % 3 - 1;
        bool valid = ((unsigned)sy < 32u) && ((unsigned)sx < 32u);
        const float* src = g_xrp + (sy * 32 + sx) * CC;
        #pragma unroll
        for (int q = 0; q < 4; q++) {
            int c = t + q * 256;
            snF[c * 9 + kidx] = valid ? src[c] : 0.f;
        }
    }
    __syncthreads();

    float pl[9];
    #pragma unroll
    for (int j = 0; j < 9; j++) pl[j] = 0.f;
    float sv[4][9];
    #pragma unroll
    for (int q = 0; q < 4; q++) {
        int cc = t + q * 256;
        float x1v = snF[cc * 9 + 4];           // center pixel = kidx 4
        #pragma unroll
        for (int j = 0; j < 9; j++) {
            float v = snF[j * 1024 + cc];      // snF[F], F = j*1024+cc
            sv[q][j] = v;
            pl[j] += x1v * v;
        }
    }
    int lane = t & 31, w = t >> 5;
    #pragma unroll
    for (int j = 0; j < 9; j++) {
        float s = pl[j];
        #pragma unroll
        for (int o = 16; o > 0; o >>= 1) s += __shfl_xor_sync(0xffffffffu, s, o);
        if (lane == 0) wsum[w][j] = s;
    }
    __syncthreads();
    if (t < 9) {
        float s = 0.f;
        #pragma unroll
        for (int i = 0; i < 8; i++) s += wsum[i][t];
        lg[t] = s;
    }
    __syncthreads();
    if (t == 0) {
        float m = lg[0];
        #pragma unroll
        for (int j = 1; j < 9; j++) m = fmaxf(m, lg[j]);
        float e[9], ss = 0.f;
        #pragma unroll
        for (int j = 0; j < 9; j++) { e[j] = __expf(lg[j] - m); ss += e[j]; }
        float inv = __fdividef(1.f, ss);
        #pragma unroll
        for (int j = 0; j < 9; j++) attn[j] = e[j] * inv;
    }
    __syncthreads();
    float at[9];
    #pragma unroll
    for (int j = 0; j < 9; j++) at[j] = attn[j];
    #pragma unroll
    for (int q = 0; q < 4; q++) {
        int cc = t + q * 256;
        float acc = 0.f;
        #pragma unroll
        for (int j = 0; j < 9; j++)
            acc += at[j] * sv[q][j];
        __nv_bfloat16 h, l;
        bsplit(acc, h, l);
        g_Bh[p * 2048 + cc] = h;
        g_Bl[p * 2048 + cc] = l;
    }
}

// =========================== mma.sync bf16-split GEMM ===========================
// D[1024][1024] = W[1024][2048] @ B^T ; CTA tile 128x64, K chunks of 64.
// 4-stage cp.async pipeline, issue-before-compute (fill slot != compute slot),
// single __syncthreads per iteration.
#define NCHUNK 32
#define NSTAGE 4
#define SSZ    49152   // Ah 16K | Al 16K | Bh 8K | Bl 8K
#define OFF_AL 16384
#define OFF_BH 32768
#define OFF_BL 40960

__device__ __forceinline__ uint32_t smem_u32(const void* p) {
    uint32_t a;
    asm("{ .reg .u64 t; cvta.to.shared.u64 t, %1; cvt.u32.u64 %0, t; }" : "=r"(a) : "l"(p));
    return a;
}
__device__ __forceinline__ void cp16(uint32_t dst, const void* src) {
    asm volatile("cp.async.ca.shared.global [%0], [%1], 16;" :: "r"(dst), "l"(src) : "memory");
}
__device__ __forceinline__ void ldsm4(uint32_t* r, uint32_t addr) {
    asm volatile("ldmatrix.sync.aligned.m8n8.x4.shared.b16 {%0,%1,%2,%3}, [%4];"
                 : "=r"(r[0]), "=r"(r[1]), "=r"(r[2]), "=r"(r[3]) : "r"(addr));
}
__device__ __forceinline__ void mma16816(float* d, const uint32_t* a, const uint32_t* b) {
    asm volatile(
        "mma.sync.aligned.m16n8k16.row.col.f32.bf16.bf16.f32 "
        "{%0,%1,%2,%3}, {%4,%5,%6,%7}, {%8,%9}, {%0,%1,%2,%3};"
        : "+f"(d[0]), "+f"(d[1]), "+f"(d[2]), "+f"(d[3])
        : "r"(a[0]), "r"(a[1]), "r"(a[2]), "r"(a[3]), "r"(b[0]), "r"(b[1]));
}

__device__ __forceinline__ void issue_chunk(char* smbase, int st, int ch,
                                            int m0, int n0, int tid) {
    uint32_t sb = smem_u32(smbase + st * SSZ);
    const char* wh = (const char*)g_Wh;
    const char* wl = (const char*)g_Wl;
    const char* bh = (const char*)g_Bh;
    const char* bl = (const char*)g_Bl;
    int kbyte = ch * 128;
    #pragma unroll
    for (int q = 0; q < 4; q++) {
        int idx = tid + q * 256;
        int row = idx >> 3, kb = idx & 7;
        int swz = row * 128 + ((kb ^ (row & 7)) << 4);
        long goff = (long)(m0 + row) * 4096 + kbyte + kb * 16;
        cp16(sb + swz,           wh + goff);
        cp16(sb + OFF_AL + swz,  wl + goff);
    }
    #pragma unroll
    for (int q = 0; q < 2; q++) {
        int idx = tid + q * 256;
        int row = idx >> 3, kb = idx & 7;
        int swz = row * 128 + ((kb ^ (row & 7)) << 4);
        long goff = (long)(n0 + row) * 4096 + kbyte + kb * 16;
        cp16(sb + OFF_BH + swz,  bh + goff);
        cp16(sb + OFF_BL + swz,  bl + goff);
    }
    asm volatile("cp.async.commit_group;" ::: "memory");
}

__global__ void __launch_bounds__(256)
k_gemm(const float* __restrict__ gamma, const float* __restrict__ beta,
       const float* __restrict__ mean, const float* __restrict__ var,
       float* __restrict__ out) {
    extern __shared__ char sm[];
    int tid = threadIdx.x;
    int wid = tid >> 5, lane = tid & 31;
    int n0 = blockIdx.x * 64;
    int m0 = blockIdx.y * 128;
    int warp_m = (wid >> 1) * 32;
    int warp_n = (wid & 1) * 32;

    issue_chunk(sm, 0, 0, m0, n0, tid);
    issue_chunk(sm, 1, 1, m0, n0, tid);
    issue_chunk(sm, 2, 2, m0, n0, tid);

    float d[2][4][4];
    #pragma unroll
    for (int i = 0; i < 2; i++)
        #pragma unroll
        for (int j = 0; j < 4; j++)
            #pragma unroll
            for (int q = 0; q < 4; q++) d[i][j][q] = 0.f;

    int a_row_in = (lane & 7) + ((lane >> 3) & 1) * 8;
    int a_kb_off = lane >> 4;
    int b_sub = lane >> 3;
    int b_row_in = lane & 7;

    for (int ch = 0; ch < NCHUNK; ch++) {
        int st = ch & (NSTAGE - 1);
        int rem = NCHUNK - 1 - ch;
        if (rem >= 2)      asm volatile("cp.async.wait_group 2;" ::: "memory");
        else if (rem == 1) asm volatile("cp.async.wait_group 1;" ::: "memory");
        else               asm volatile("cp.async.wait_group 0;" ::: "memory");
        __syncthreads();

        // fill slot (ch+3)&3 != compute slot ch&3: loads overlap this chunk's MMAs
        if (ch + 3 < NCHUNK)
            issue_chunk(sm, (ch + 3) & (NSTAGE - 1), ch + 3, m0, n0, tid);

        uint32_t sb = smem_u32(sm + st * SSZ);
        #pragma unroll
        for (int ks = 0; ks < 4; ks++) {
            uint32_t ah[2][4], al[2][4], bhf[4][2], blf[4][2];
            #pragma unroll
            for (int mt = 0; mt < 2; mt++) {
                int row = warp_m + mt * 16 + a_row_in;
                int kb = 2 * ks + a_kb_off;
                uint32_t ad = sb + row * 128 + ((kb ^ (row & 7)) << 4);
                ldsm4(ah[mt], ad);
                ldsm4(al[mt], ad + OFF_AL);
            }
            #pragma unroll
            for (int q = 0; q < 2; q++) {
                int row = warp_n + (2 * q + (b_sub >> 1)) * 8 + b_row_in;
                int kb = 2 * ks + (b_sub & 1);
                uint32_t bd = sb + OFF_BH + row * 128 + ((kb ^ (row & 7)) << 4);
                uint32_t r[4];
                ldsm4(r, bd);
                bhf[2 * q][0] = r[0]; bhf[2 * q][1] = r[1];
                bhf[2 * q + 1][0] = r[2]; bhf[2 * q + 1][1] = r[3];
                ldsm4(r, bd + (OFF_BL - OFF_BH));
                blf[2 * q][0] = r[0]; blf[2 * q][1] = r[1];
                blf[2 * q + 1][0] = r[2]; blf[2 * q + 1][1] = r[3];
            }
            #pragma unroll
            for (int mt = 0; mt < 2; mt++)
                #pragma unroll
                for (int nt = 0; nt < 4; nt++) {
                    mma16816(d[mt][nt], ah[mt], bhf[nt]);
                    mma16816(d[mt][nt], ah[mt], blf[nt]);
                    mma16816(d[mt][nt], al[mt], bhf[nt]);
                }
        }
        // no trailing sync: next iteration's sync (after wait) orders compute
        // completion before any warp refills this slot
    }

    int r4 = lane >> 2, c2 = (lane & 3) * 2;
    #pragma unroll
    for (int mt = 0; mt < 2; mt++) {
        int o0 = m0 + warp_m + mt * 16 + r4;
        int o1 = o0 + 8;
        float i0 = rsqrtf(var[o0] + 1e-5f) * gamma[o0];
        float i1 = rsqrtf(var[o1] + 1e-5f) * gamma[o1];
        float u0 = mean[o0], u1 = mean[o1];
        float t0 = beta[o0], t1 = beta[o1];
        #pragma unroll
        for (int nt = 0; nt < 4; nt++) {
            int col = n0 + warp_n + nt * 8 + c2;
            float2 v0, v1;
            v0.x = fmaxf((d[mt][nt][0] - u0) * i0 + t0, 0.f);
            v0.y = fmaxf((d[mt][nt][1] - u0) * i0 + t0, 0.f);
            v1.x = fmaxf((d[mt][nt][2] - u1) * i1 + t1, 0.f);
            v1.y = fmaxf((d[mt][nt][3] - u1) * i1 + t1, 0.f);
            *(float2*)(out + o0 * 1024 + col) = v0;
            *(float2*)(out + o1 * 1024 + col) = v1;
        }
    }
}

extern "C" void kernel_launch(void* const* d_in, const int* in_sizes, int n_in,
                              void* d_out, int out_size) {
    const float* x     = (const float*)d_in[0];
    const float* w1    = (const float*)d_in[1];
    const float* b1    = (const float*)d_in[2];
    const float* w2    = (const float*)d_in[3];
    const float* b2    = (const float*)d_in[4];
    const float* cw    = (const float*)d_in[5];
    const float* gamma = (const float*)d_in[6];
    const float* beta  = (const float*)d_in[7];
    const float* mean  = (const float*)d_in[8];
    const float* var   = (const float*)d_in[9];
    float* out = (float*)d_out;

    cudaFuncSetAttribute(k_gemm, cudaFuncAttributeMaxDynamicSharedMemorySize, NSTAGE * SSZ);

    k_prep<<<2049, 256>>>(cw, x);                         // 0
    k_se<<<32, 256>>>(w1, b1, w2, b2);                    // 1
    k_chan8<<<128, 512>>>(x);                             // 2
    k_attn<<<1024, 256>>>();                              // 3  <- profiled (clock canary: ~11us)
    k_gemm<<<dim3(16, 8), 256, NSTAGE * SSZ>>>(gamma, beta, mean, var, out);  // 4
}

// round 15
// speedup vs baseline: 1.1756x; 1.1756x over previous
#include <cuda_runtime.h>
#include <cuda_bf16.h>
#include <cuda_fp16.h>
#include <math.h>
#include <stdint.h>

#define HW 1024
#define CC 1024
#define CR 64

__device__ __forceinline__ float fsigmoid(float v) {
    return __fdividef(1.f, 1.f + __expf(-v));
}

// ---------------- scratch ----------------
__device__ float g_A[32 * 32];
__device__ float g_mean[CC];
__device__ float g_scale[CC];
__device__ float g_xrp[HW * CC];            // sigmoid(x_se), pixel-major [p][c]
__device__ __half g_Wh[1024 * 2048];        // conv weight fp16 hi/lo split (exact pair)
__device__ __half g_Wl[1024 * 2048];
__device__ __half g_B[HW * 2048];           // GEMM B, fp16 single, K-major [p][k]

// ---------------- split helper (fp16 hi + residual lo) ----------------
__device__ __forceinline__ void hsplit(float v, __half& h, __half& l) {
    h = __float2half(v);
    l = __float2half(v - __half2float(h));
}

// ---------------- fused prep: convW split | per-channel mean | gaussian table ------
__global__ void k_prep(const float* __restrict__ w, const float* __restrict__ x) {
    int b = blockIdx.x;
    int t = threadIdx.x;   // 256
    if (b < 1024) {
        int base = (b * 256 + t) * 8;
        float4 v0 = *(const float4*)(w + base);
        float4 v1 = *(const float4*)(w + base + 4);
        __half h[8], l[8];
        float vv[8] = {v0.x, v0.y, v0.z, v0.w, v1.x, v1.y, v1.z, v1.w};
        #pragma unroll
        for (int i = 0; i < 8; i++) hsplit(vv[i], h[i], l[i]);
        *(uint4*)(g_Wh + base) = *(uint4*)h;
        *(uint4*)(g_Wl + base) = *(uint4*)l;
    } else if (b < 2048) {
        int c = b - 1024;
        const float* xc = x + c * HW;
        float s = 0.f;
        #pragma unroll
        for (int q = 0; q < 4; q++) s += xc[t + q * 256];
        #pragma unroll
        for (int o = 16; o > 0; o >>= 1) s += __shfl_xor_sync(0xffffffffu, s, o);
        __shared__ float red[8];
        int lane = t & 31, wv = t >> 5;
        if (lane == 0) red[wv] = s;
        __syncthreads();
        if (t == 0) {
            float tt = 0.f;
            #pragma unroll
            for (int i = 0; i < 8; i++) tt += red[i];
            g_mean[c] = tt * (1.0f / 1024.0f);
        }
    } else {
        // 1D gaussian table, row-normalized
        int i = t >> 3;
        int x0 = (t & 7) * 4;
        float e[4], s = 0.f;
        #pragma unroll
        for (int q = 0; q < 4; q++) {
            float d = (float)(i - (x0 + q));
            e[q] = __expf(-d * d / 4.5f);
            s += e[q];
        }
        s += __shfl_xor_sync(0xffffffffu, s, 1);
        s += __shfl_xor_sync(0xffffffffu, s, 2);
        s += __shfl_xor_sync(0xffffffffu, s, 4);
        float inv = __fdividef(1.f, s);
        #pragma unroll
        for (int q = 0; q < 4; q++) g_A[i * 32 + x0 + q] = e[q] * inv;
    }
}

// ---------------- fused SE: scale = sigmoid(W2 relu(W1 mean + b1) + b2) ------------
__global__ void k_se(const float* __restrict__ w1, const float* __restrict__ b1,
                     const float* __restrict__ w2, const float* __restrict__ b2) {
    __shared__ float ym[CC];
    __shared__ float h1s[CR];
    int t = threadIdx.x;   // 256
    int w = t >> 5, lane = t & 31;
    #pragma unroll
    for (int q = 0; q < 4; q++) ym[t + q * 256] = g_mean[t + q * 256];
    __syncthreads();
    #pragma unroll
    for (int jj = 0; jj < 8; jj++) {
        int j = w * 8 + jj;
        const float* wr = w1 + j * CC;
        float s = 0.f;
        #pragma unroll
        for (int k = 0; k < 32; k++) s += wr[lane + k * 32] * ym[lane + k * 32];
        #pragma unroll
        for (int o = 16; o > 0; o >>= 1) s += __shfl_xor_sync(0xffffffffu, s, o);
        if (lane == 0) h1s[j] = fmaxf(s + b1[j], 0.f);
    }
    __syncthreads();
    int gid = blockIdx.x * 256 + t;
    int c = gid >> 3, l8 = gid & 7;
    const float* wr = w2 + c * CR;
    float s = 0.f;
    #pragma unroll
    for (int k = 0; k < 8; k++) s += wr[l8 + k * 8] * h1s[l8 + k * 8];
    s += __shfl_xor_sync(0xffffffffu, s, 1);
    s += __shfl_xor_sync(0xffffffffu, s, 2);
    s += __shfl_xor_sync(0xffffffffu, s, 4);
    if (l8 == 0) g_scale[c] = fsigmoid(s + b2[c]);
}

// ---------------- fused channel stage: 8 channels/block, 128 blocks, 512 threads ---
__global__ void __launch_bounds__(512)
k_chan8(const float* __restrict__ x) {
    __shared__ float xs[8][1024];
    __shared__ float At[32][36];    // At[y][k] = A[k][y]
    __shared__ float tm[32][36];
    int c0 = blockIdx.x * 8;
    int t = threadIdx.x;            // 512

    if (t < 256) {
        #pragma unroll
        for (int q = 0; q < 4; q++) {
            int i = t + q * 256;    // i = k*32 + y
            At[i & 31][i >> 5] = g_A[i];
        }
    }
    #pragma unroll
    for (int i = 0; i < 8; i++) {
        float sc = g_scale[c0 + i];
        #pragma unroll
        for (int q = 0; q < 2; q++) {
            int p = t + q * 512;
            xs[i][p] = x[(c0 + i) * HW + p] * sc;
        }
    }
    __syncthreads();

    #pragma unroll
    for (int q = 0; q < 2; q++) {
        int p = t + q * 512;
        float v[8];
        #pragma unroll
        for (int i = 0; i < 8; i++) v[i] = fsigmoid(xs[i][p]);
        *(float4*)(g_xrp + p * CC + c0)     = make_float4(v[0], v[1], v[2], v[3]);
        *(float4*)(g_xrp + p * CC + c0 + 4) = make_float4(v[4], v[5], v[6], v[7]);
    }

    int xrow = t >> 4, k2 = (t & 15) * 2;
    #pragma unroll
    for (int i = 0; i < 8; i++) {
        float a0 = 0.f, a1 = 0.f;
        #pragma unroll
        for (int y = 0; y < 32; y++) {
            float xv = xs[i][xrow * 32 + y];
            a0 += xv * At[y][k2];
            a1 += xv * At[y][k2 + 1];
        }
        __syncthreads();
        tm[xrow][k2] = a0;
        tm[xrow][k2 + 1] = a1;
        __syncthreads();
        float o0 = 0.f, o1 = 0.f;
        #pragma unroll
        for (int xx = 0; xx < 32; xx++) {
            float av = At[xx][xrow];
            o0 += av * tm[xx][k2];
            o1 += av * tm[xx][k2 + 1];
        }
        __syncthreads();
        xs[i][xrow * 32 + k2] = o0;
        xs[i][xrow * 32 + k2 + 1] = o1;
    }
    __syncthreads();

    // spat half of B: per pixel, 8 contiguous fp16 (one uint4)
    #pragma unroll
    for (int q = 0; q < 2; q++) {
        int p = t + q * 512;
        __half h[8];
        #pragma unroll
        for (int i = 0; i < 8; i++) h[i] = __float2half(xs[i][p]);
        *(uint4*)(g_B + p * 2048 + 1024 + c0) = *(uint4*)h;
    }
}

// ---------------- scrambled 3x3 softmax attention -> B (k<1024) ----------------
// snF[F] = neighbor_row[F%9][F/9] (stride-9 scatter fill, conflict-free). Linear
// addressing in hot loops + register cache sv[][] so pass 2 does zero LDS.
__global__ void k_attn() {
    __shared__ float snF[9216];     // [c*9 + kidx]
    __shared__ float wsum[8][9];
    __shared__ float lg[9];
    __shared__ float attn[9];
    int p = blockIdx.x;
    int py = p >> 5, px = p & 31;
    int t = threadIdx.x;  // 256

    #pragma unroll
    for (int kidx = 0; kidx < 9; kidx++) {
        int sy = py + kidx / 3 - 1;
        int sx = px + kidx % 3 - 1;
        bool valid = ((unsigned)sy < 32u) && ((unsigned)sx < 32u);
        const float* src = g_xrp + (sy * 32 + sx) * CC;
        #pragma unroll
        for (int q = 0; q < 4; q++) {
            int c = t + q * 256;
            snF[c * 9 + kidx] = valid ? src[c] : 0.f;
        }
    }
    __syncthreads();

    float pl[9];
    #pragma unroll
    for (int j = 0; j < 9; j++) pl[j] = 0.f;
    float sv[4][9];
    #pragma unroll
    for (int q = 0; q < 4; q++) {
        int cc = t + q * 256;
        float x1v = snF[cc * 9 + 4];           // center pixel = kidx 4
        #pragma unroll
        for (int j = 0; j < 9; j++) {
            float v = snF[j * 1024 + cc];      // snF[F], F = j*1024+cc
            sv[q][j] = v;
            pl[j] += x1v * v;
        }
    }
    int lane = t & 31, w = t >> 5;
    #pragma unroll
    for (int j = 0; j < 9; j++) {
        float s = pl[j];
        #pragma unroll
        for (int o = 16; o > 0; o >>= 1) s += __shfl_xor_sync(0xffffffffu, s, o);
        if (lane == 0) wsum[w][j] = s;
    }
    __syncthreads();
    if (t < 9) {
        float s = 0.f;
        #pragma unroll
        for (int i = 0; i < 8; i++) s += wsum[i][t];
        lg[t] = s;
    }
    __syncthreads();
    if (t == 0) {
        float m = lg[0];
        #pragma unroll
        for (int j = 1; j < 9; j++) m = fmaxf(m, lg[j]);
        float e[9], ss = 0.f;
        #pragma unroll
        for (int j = 0; j < 9; j++) { e[j] = __expf(lg[j] - m); ss += e[j]; }
        float inv = __fdividef(1.f, ss);
        #pragma unroll
        for (int j = 0; j < 9; j++) attn[j] = e[j] * inv;
    }
    __syncthreads();
    float at[9];
    #pragma unroll
    for (int j = 0; j < 9; j++) at[j] = attn[j];
    #pragma unroll
    for (int q = 0; q < 4; q++) {
        int cc = t + q * 256;
        float acc = 0.f;
        #pragma unroll
        for (int j = 0; j < 9; j++)
            acc += at[j] * sv[q][j];
        g_B[p * 2048 + cc] = __float2half(acc);
    }
}

// =========================== mma.sync fp16 2-term GEMM ===========================
// D[1024][1024] = W[1024][2048] @ B^T, W = Wh + Wl (exact fp16 pair), B fp16.
// D = Ah*B + Al*B : 16 MMAs per k16-step (was 24). CTA tile 128x64, K chunks of 64,
// 4-stage cp.async, issue-before-compute, single sync per iteration.
#define NCHUNK 32
#define NSTAGE 4
#define SSZ    40960   // Ah 16K | Al 16K | B 8K
#define OFF_AL 16384
#define OFF_B  32768

__device__ __forceinline__ uint32_t smem_u32(const void* p) {
    uint32_t a;
    asm("{ .reg .u64 t; cvta.to.shared.u64 t, %1; cvt.u32.u64 %0, t; }" : "=r"(a) : "l"(p));
    return a;
}
__device__ __forceinline__ void cp16(uint32_t dst, const void* src) {
    asm volatile("cp.async.ca.shared.global [%0], [%1], 16;" :: "r"(dst), "l"(src) : "memory");
}
__device__ __forceinline__ void ldsm4(uint32_t* r, uint32_t addr) {
    asm volatile("ldmatrix.sync.aligned.m8n8.x4.shared.b16 {%0,%1,%2,%3}, [%4];"
                 : "=r"(r[0]), "=r"(r[1]), "=r"(r[2]), "=r"(r[3]) : "r"(addr));
}
__device__ __forceinline__ void mma16816(float* d, const uint32_t* a, const uint32_t* b) {
    asm volatile(
        "mma.sync.aligned.m16n8k16.row.col.f32.f16.f16.f32 "
        "{%0,%1,%2,%3}, {%4,%5,%6,%7}, {%8,%9}, {%0,%1,%2,%3};"
        : "+f"(d[0]), "+f"(d[1]), "+f"(d[2]), "+f"(d[3])
        : "r"(a[0]), "r"(a[1]), "r"(a[2]), "r"(a[3]), "r"(b[0]), "r"(b[1]));
}

__device__ __forceinline__ void issue_chunk(char* smbase, int st, int ch,
                                            int m0, int n0, int tid) {
    uint32_t sb = smem_u32(smbase + st * SSZ);
    const char* wh = (const char*)g_Wh;
    const char* wl = (const char*)g_Wl;
    const char* bb = (const char*)g_B;
    int kbyte = ch * 128;   // 64 fp16 = 128 bytes per chunk
    #pragma unroll
    for (int q = 0; q < 4; q++) {
        int idx = tid + q * 256;
        int row = idx >> 3, kb = idx & 7;
        int swz = row * 128 + ((kb ^ (row & 7)) << 4);
        long goff = (long)(m0 + row) * 4096 + kbyte + kb * 16;
        cp16(sb + swz,           wh + goff);
        cp16(sb + OFF_AL + swz,  wl + goff);
    }
    #pragma unroll
    for (int q = 0; q < 2; q++) {
        int idx = tid + q * 256;
        int row = idx >> 3, kb = idx & 7;
        int swz = row * 128 + ((kb ^ (row & 7)) << 4);
        long goff = (long)(n0 + row) * 4096 + kbyte + kb * 16;
        cp16(sb + OFF_B + swz,   bb + goff);
    }
    asm volatile("cp.async.commit_group;" ::: "memory");
}

__global__ void __launch_bounds__(256)
k_gemm(const float* __restrict__ gamma, const float* __restrict__ beta,
       const float* __restrict__ mean, const float* __restrict__ var,
       float* __restrict__ out) {
    extern __shared__ char sm[];
    int tid = threadIdx.x;
    int wid = tid >> 5, lane = tid & 31;
    int n0 = blockIdx.x * 64;
    int m0 = blockIdx.y * 128;
    int warp_m = (wid >> 1) * 32;
    int warp_n = (wid & 1) * 32;

    issue_chunk(sm, 0, 0, m0, n0, tid);
    issue_chunk(sm, 1, 1, m0, n0, tid);
    issue_chunk(sm, 2, 2, m0, n0, tid);

    float d[2][4][4];
    #pragma unroll
    for (int i = 0; i < 2; i++)
        #pragma unroll
        for (int j = 0; j < 4; j++)
            #pragma unroll
            for (int q = 0; q < 4; q++) d[i][j][q] = 0.f;

    int a_row_in = (lane & 7) + ((lane >> 3) & 1) * 8;
    int a_kb_off = lane >> 4;
    int b_sub = lane >> 3;
    int b_row_in = lane & 7;

    for (int ch = 0; ch < NCHUNK; ch++) {
        int st = ch & (NSTAGE - 1);
        int rem = NCHUNK - 1 - ch;
        if (rem >= 2)      asm volatile("cp.async.wait_group 2;" ::: "memory");
        else if (rem == 1) asm volatile("cp.async.wait_group 1;" ::: "memory");
        else               asm volatile("cp.async.wait_group 0;" ::: "memory");
        __syncthreads();

        if (ch + 3 < NCHUNK)
            issue_chunk(sm, (ch + 3) & (NSTAGE - 1), ch + 3, m0, n0, tid);

        uint32_t sb = smem_u32(sm + st * SSZ);
        #pragma unroll
        for (int ks = 0; ks < 4; ks++) {
            uint32_t ah[2][4], al[2][4], bf[4][2];
            #pragma unroll
            for (int mt = 0; mt < 2; mt++) {
                int row = warp_m + mt * 16 + a_row_in;
                int kb = 2 * ks + a_kb_off;
                uint32_t ad = sb + row * 128 + ((kb ^ (row & 7)) << 4);
                ldsm4(ah[mt], ad);
                ldsm4(al[mt], ad + OFF_AL);
            }
            #pragma unroll
            for (int q = 0; q < 2; q++) {
                int row = warp_n + (2 * q + (b_sub >> 1)) * 8 + b_row_in;
                int kb = 2 * ks + (b_sub & 1);
                uint32_t bd = sb + OFF_B + row * 128 + ((kb ^ (row & 7)) << 4);
                uint32_t r[4];
                ldsm4(r, bd);
                bf[2 * q][0] = r[0]; bf[2 * q][1] = r[1];
                bf[2 * q + 1][0] = r[2]; bf[2 * q + 1][1] = r[3];
            }
            #pragma unroll
            for (int mt = 0; mt < 2; mt++)
                #pragma unroll
                for (int nt = 0; nt < 4; nt++) {
                    mma16816(d[mt][nt], ah[mt], bf[nt]);
                    mma16816(d[mt][nt], al[mt], bf[nt]);
                }
        }
    }

    int r4 = lane >> 2, c2 = (lane & 3) * 2;
    #pragma unroll
    for (int mt = 0; mt < 2; mt++) {
        int o0 = m0 + warp_m + mt * 16 + r4;
        int o1 = o0 + 8;
        float i0 = rsqrtf(var[o0] + 1e-5f) * gamma[o0];
        float i1 = rsqrtf(var[o1] + 1e-5f) * gamma[o1];
        float u0 = mean[o0], u1 = mean[o1];
        float t0 = beta[o0], t1 = beta[o1];
        #pragma unroll
        for (int nt = 0; nt < 4; nt++) {
            int col = n0 + warp_n + nt * 8 + c2;
            float2 v0, v1;
            v0.x = fmaxf((d[mt][nt][0] - u0) * i0 + t0, 0.f);
            v0.y = fmaxf((d[mt][nt][1] - u0) * i0 + t0, 0.f);
            v1.x = fmaxf((d[mt][nt][2] - u1) * i1 + t1, 0.f);
            v1.y = fmaxf((d[mt][nt][3] - u1) * i1 + t1, 0.f);
            *(float2*)(out + o0 * 1024 + col) = v0;
            *(float2*)(out + o1 * 1024 + col) = v1;
        }
    }
}

extern "C" void kernel_launch(void* const* d_in, const int* in_sizes, int n_in,
                              void* d_out, int out_size) {
    const float* x     = (const float*)d_in[0];
    const float* w1    = (const float*)d_in[1];
    const float* b1    = (const float*)d_in[2];
    const float* w2    = (const float*)d_in[3];
    const float* b2    = (const float*)d_in[4];
    const float* cw    = (const float*)d_in[5];
    const float* gamma = (const float*)d_in[6];
    const float* beta  = (const float*)d_in[7];
    const float* mean  = (const float*)d_in[8];
    const float* var   = (const float*)d_in[9];
    float* out = (float*)d_out;

    cudaFuncSetAttribute(k_gemm, cudaFuncAttributeMaxDynamicSharedMemorySize, NSTAGE * SSZ);

    k_prep<<<2049, 256>>>(cw, x);                         // 0
    k_se<<<32, 256>>>(w1, b1, w2, b2);                    // 1
    k_chan8<<<128, 512>>>(x);                             // 2
    k_attn<<<1024, 256>>>();                              // 3  <- profiled (clock canary: ~11us)
    k_gemm<<<dim3(16, 8), 256, NSTAGE * SSZ>>>(gamma, beta, mean, var, out);  // 4
}

// round 16
// speedup vs baseline: 1.3910x; 1.1832x over previous
#include <cuda_runtime.h>
#include <cuda_bf16.h>
#include <cuda_fp16.h>
#include <math.h>
#include <stdint.h>

#define HW 1024
#define CC 1024
#define CR 64

__device__ __forceinline__ float fsigmoid(float v) {
    return __fdividef(1.f, 1.f + __expf(-v));
}

// ---------------- scratch ----------------
__device__ float g_A[32 * 32];
__device__ float g_mean[CC];
__device__ float g_scale[CC];
__device__ float g_xrp[HW * CC];            // sigmoid(x_se), pixel-major [p][c]
__device__ __half g_W[1024 * 2048];         // conv weight, fp16
__device__ __half g_B[HW * 2048];           // GEMM B, fp16, K-major [p][k]

// ---------------- fused prep: convW fp16 | per-channel mean | gaussian table ------
__global__ void k_prep(const float* __restrict__ w, const float* __restrict__ x) {
    int b = blockIdx.x;
    int t = threadIdx.x;   // 256
    if (b < 1024) {
        int base = (b * 256 + t) * 8;
        float4 v0 = *(const float4*)(w + base);
        float4 v1 = *(const float4*)(w + base + 4);
        __half h[8];
        float vv[8] = {v0.x, v0.y, v0.z, v0.w, v1.x, v1.y, v1.z, v1.w};
        #pragma unroll
        for (int i = 0; i < 8; i++) h[i] = __float2half(vv[i]);
        *(uint4*)(g_W + base) = *(uint4*)h;
    } else if (b < 2048) {
        int c = b - 1024;
        const float* xc = x + c * HW;
        float s = 0.f;
        #pragma unroll
        for (int q = 0; q < 4; q++) s += xc[t + q * 256];
        #pragma unroll
        for (int o = 16; o > 0; o >>= 1) s += __shfl_xor_sync(0xffffffffu, s, o);
        __shared__ float red[8];
        int lane = t & 31, wv = t >> 5;
        if (lane == 0) red[wv] = s;
        __syncthreads();
        if (t == 0) {
            float tt = 0.f;
            #pragma unroll
            for (int i = 0; i < 8; i++) tt += red[i];
            g_mean[c] = tt * (1.0f / 1024.0f);
        }
    } else {
        // 1D gaussian table, row-normalized
        int i = t >> 3;
        int x0 = (t & 7) * 4;
        float e[4], s = 0.f;
        #pragma unroll
        for (int q = 0; q < 4; q++) {
            float d = (float)(i - (x0 + q));
            e[q] = __expf(-d * d / 4.5f);
            s += e[q];
        }
        s += __shfl_xor_sync(0xffffffffu, s, 1);
        s += __shfl_xor_sync(0xffffffffu, s, 2);
        s += __shfl_xor_sync(0xffffffffu, s, 4);
        float inv = __fdividef(1.f, s);
        #pragma unroll
        for (int q = 0; q < 4; q++) g_A[i * 32 + x0 + q] = e[q] * inv;
    }
}

// ---------------- fused SE: scale = sigmoid(W2 relu(W1 mean + b1) + b2) ------------
__global__ void k_se(const float* __restrict__ w1, const float* __restrict__ b1,
                     const float* __restrict__ w2, const float* __restrict__ b2) {
    __shared__ float ym[CC];
    __shared__ float h1s[CR];
    int t = threadIdx.x;   // 256
    int w = t >> 5, lane = t & 31;
    #pragma unroll
    for (int q = 0; q < 4; q++) ym[t + q * 256] = g_mean[t + q * 256];
    __syncthreads();
    #pragma unroll
    for (int jj = 0; jj < 8; jj++) {
        int j = w * 8 + jj;
        const float* wr = w1 + j * CC;
        float s = 0.f;
        #pragma unroll
        for (int k = 0; k < 32; k++) s += wr[lane + k * 32] * ym[lane + k * 32];
        #pragma unroll
        for (int o = 16; o > 0; o >>= 1) s += __shfl_xor_sync(0xffffffffu, s, o);
        if (lane == 0) h1s[j] = fmaxf(s + b1[j], 0.f);
    }
    __syncthreads();
    int gid = blockIdx.x * 256 + t;
    int c = gid >> 3, l8 = gid & 7;
    const float* wr = w2 + c * CR;
    float s = 0.f;
    #pragma unroll
    for (int k = 0; k < 8; k++) s += wr[l8 + k * 8] * h1s[l8 + k * 8];
    s += __shfl_xor_sync(0xffffffffu, s, 1);
    s += __shfl_xor_sync(0xffffffffu, s, 2);
    s += __shfl_xor_sync(0xffffffffu, s, 4);
    if (l8 == 0) g_scale[c] = fsigmoid(s + b2[c]);
}

// ---------------- fused channel stage: 8 channels/block, 128 blocks, 512 threads ---
__global__ void __launch_bounds__(512)
k_chan8(const float* __restrict__ x) {
    __shared__ float xs[8][1024];
    __shared__ float At[32][36];    // At[y][k] = A[k][y]
    __shared__ float tm[32][36];
    int c0 = blockIdx.x * 8;
    int t = threadIdx.x;            // 512

    if (t < 256) {
        #pragma unroll
        for (int q = 0; q < 4; q++) {
            int i = t + q * 256;    // i = k*32 + y
            At[i & 31][i >> 5] = g_A[i];
        }
    }
    #pragma unroll
    for (int i = 0; i < 8; i++) {
        float sc = g_scale[c0 + i];
        #pragma unroll
        for (int q = 0; q < 2; q++) {
            int p = t + q * 512;
            xs[i][p] = x[(c0 + i) * HW + p] * sc;
        }
    }
    __syncthreads();

    #pragma unroll
    for (int q = 0; q < 2; q++) {
        int p = t + q * 512;
        float v[8];
        #pragma unroll
        for (int i = 0; i < 8; i++) v[i] = fsigmoid(xs[i][p]);
        *(float4*)(g_xrp + p * CC + c0)     = make_float4(v[0], v[1], v[2], v[3]);
        *(float4*)(g_xrp + p * CC + c0 + 4) = make_float4(v[4], v[5], v[6], v[7]);
    }

    int xrow = t >> 4, k2 = (t & 15) * 2;
    #pragma unroll
    for (int i = 0; i < 8; i++) {
        float a0 = 0.f, a1 = 0.f;
        #pragma unroll
        for (int y = 0; y < 32; y++) {
            float xv = xs[i][xrow * 32 + y];
            a0 += xv * At[y][k2];
            a1 += xv * At[y][k2 + 1];
        }
        __syncthreads();
        tm[xrow][k2] = a0;
        tm[xrow][k2 + 1] = a1;
        __syncthreads();
        float o0 = 0.f, o1 = 0.f;
        #pragma unroll
        for (int xx = 0; xx < 32; xx++) {
            float av = At[xx][xrow];
            o0 += av * tm[xx][k2];
            o1 += av * tm[xx][k2 + 1];
        }
        __syncthreads();
        xs[i][xrow * 32 + k2] = o0;
        xs[i][xrow * 32 + k2 + 1] = o1;
    }
    __syncthreads();

    // spat half of B: per pixel, 8 contiguous fp16 (one uint4)
    #pragma unroll
    for (int q = 0; q < 2; q++) {
        int p = t + q * 512;
        __half h[8];
        #pragma unroll
        for (int i = 0; i < 8; i++) h[i] = __float2half(xs[i][p]);
        *(uint4*)(g_B + p * 2048 + 1024 + c0) = *(uint4*)h;
    }
}

// ---------------- scrambled 3x3 softmax attention -> B (k<1024) ----------------
// snF[F] = neighbor_row[F%9][F/9] (stride-9 scatter fill, conflict-free). Linear
// addressing in hot loops + register cache sv[][] so pass 2 does zero LDS.
__global__ void k_attn() {
    __shared__ float snF[9216];     // [c*9 + kidx]
    __shared__ float wsum[8][9];
    __shared__ float lg[9];
    __shared__ float attn[9];
    int p = blockIdx.x;
    int py = p >> 5, px = p & 31;
    int t = threadIdx.x;  // 256

    #pragma unroll
    for (int kidx = 0; kidx < 9; kidx++) {
        int sy = py + kidx / 3 - 1;
        int sx = px + kidx % 3 - 1;
        bool valid = ((unsigned)sy < 32u) && ((unsigned)sx < 32u);
        const float* src = g_xrp + (sy * 32 + sx) * CC;
        #pragma unroll
        for (int q = 0; q < 4; q++) {
            int c = t + q * 256;
            snF[c * 9 + kidx] = valid ? src[c] : 0.f;
        }
    }
    __syncthreads();

    float pl[9];
    #pragma unroll
    for (int j = 0; j < 9; j++) pl[j] = 0.f;
    float sv[4][9];
    #pragma unroll
    for (int q = 0; q < 4; q++) {
        int cc = t + q * 256;
        float x1v = snF[cc * 9 + 4];           // center pixel = kidx 4
        #pragma unroll
        for (int j = 0; j < 9; j++) {
            float v = snF[j * 1024 + cc];      // snF[F], F = j*1024+cc
            sv[q][j] = v;
            pl[j] += x1v * v;
        }
    }
    int lane = t & 31, w = t >> 5;
    #pragma unroll
    for (int j = 0; j < 9; j++) {
        float s = pl[j];
        #pragma unroll
        for (int o = 16; o > 0; o >>= 1) s += __shfl_xor_sync(0xffffffffu, s, o);
        if (lane == 0) wsum[w][j] = s;
    }
    __syncthreads();
    if (t < 9) {
        float s = 0.f;
        #pragma unroll
        for (int i = 0; i < 8; i++) s += wsum[i][t];
        lg[t] = s;
    }
    __syncthreads();
    if (t == 0) {
        float m = lg[0];
        #pragma unroll
        for (int j = 1; j < 9; j++) m = fmaxf(m, lg[j]);
        float e[9], ss = 0.f;
        #pragma unroll
        for (int j = 0; j < 9; j++) { e[j] = __expf(lg[j] - m); ss += e[j]; }
        float inv = __fdividef(1.f, ss);
        #pragma unroll
        for (int j = 0; j < 9; j++) attn[j] = e[j] * inv;
    }
    __syncthreads();
    float at[9];
    #pragma unroll
    for (int j = 0; j < 9; j++) at[j] = attn[j];
    #pragma unroll
    for (int q = 0; q < 4; q++) {
        int cc = t + q * 256;
        float acc = 0.f;
        #pragma unroll
        for (int j = 0; j < 9; j++)
            acc += at[j] * sv[q][j];
        g_B[p * 2048 + cc] = __float2half(acc);
    }
}

// =========================== mma.sync fp16 single-term GEMM ===========================
// D[1024][1024] = W[1024][2048] @ B^T, W and B fp16.
// 8 MMAs per k16-step. CTA tile 128x64, K chunks of 64, 4-stage cp.async,
// issue-before-compute, single sync per iteration.
#define NCHUNK 32
#define NSTAGE 4
#define SSZ    24576   // A 16K | B 8K
#define OFF_B  16384

__device__ __forceinline__ uint32_t smem_u32(const void* p) {
    uint32_t a;
    asm("{ .reg .u64 t; cvta.to.shared.u64 t, %1; cvt.u32.u64 %0, t; }" : "=r"(a) : "l"(p));
    return a;
}
__device__ __forceinline__ void cp16(uint32_t dst, const void* src) {
    asm volatile("cp.async.ca.shared.global [%0], [%1], 16;" :: "r"(dst), "l"(src) : "memory");
}
__device__ __forceinline__ void ldsm4(uint32_t* r, uint32_t addr) {
    asm volatile("ldmatrix.sync.aligned.m8n8.x4.shared.b16 {%0,%1,%2,%3}, [%4];"
                 : "=r"(r[0]), "=r"(r[1]), "=r"(r[2]), "=r"(r[3]) : "r"(addr));
}
__device__ __forceinline__ void mma16816(float* d, const uint32_t* a, const uint32_t* b) {
    asm volatile(
        "mma.sync.aligned.m16n8k16.row.col.f32.f16.f16.f32 "
        "{%0,%1,%2,%3}, {%4,%5,%6,%7}, {%8,%9}, {%0,%1,%2,%3};"
        : "+f"(d[0]), "+f"(d[1]), "+f"(d[2]), "+f"(d[3])
        : "r"(a[0]), "r"(a[1]), "r"(a[2]), "r"(a[3]), "r"(b[0]), "r"(b[1]));
}

__device__ __forceinline__ void issue_chunk(char* smbase, int st, int ch,
                                            int m0, int n0, int tid) {
    uint32_t sb = smem_u32(smbase + st * SSZ);
    const char* ww = (const char*)g_W;
    const char* bb = (const char*)g_B;
    int kbyte = ch * 128;   // 64 fp16 = 128 bytes per chunk
    #pragma unroll
    for (int q = 0; q < 4; q++) {
        int idx = tid + q * 256;
        int row = idx >> 3, kb = idx & 7;
        int swz = row * 128 + ((kb ^ (row & 7)) << 4);
        long goff = (long)(m0 + row) * 4096 + kbyte + kb * 16;
        cp16(sb + swz, ww + goff);
    }
    #pragma unroll
    for (int q = 0; q < 2; q++) {
        int idx = tid + q * 256;
        int row = idx >> 3, kb = idx & 7;
        int swz = row * 128 + ((kb ^ (row & 7)) << 4);
        long goff = (long)(n0 + row) * 4096 + kbyte + kb * 16;
        cp16(sb + OFF_B + swz, bb + goff);
    }
    asm volatile("cp.async.commit_group;" ::: "memory");
}

__global__ void __launch_bounds__(256)
k_gemm(const float* __restrict__ gamma, const float* __restrict__ beta,
       const float* __restrict__ mean, const float* __restrict__ var,
       float* __restrict__ out) {
    extern __shared__ char sm[];
    int tid = threadIdx.x;
    int wid = tid >> 5, lane = tid & 31;
    int n0 = blockIdx.x * 64;
    int m0 = blockIdx.y * 128;
    int warp_m = (wid >> 1) * 32;
    int warp_n = (wid & 1) * 32;

    issue_chunk(sm, 0, 0, m0, n0, tid);
    issue_chunk(sm, 1, 1, m0, n0, tid);
    issue_chunk(sm, 2, 2, m0, n0, tid);

    float d[2][4][4];
    #pragma unroll
    for (int i = 0; i < 2; i++)
        #pragma unroll
        for (int j = 0; j < 4; j++)
            #pragma unroll
            for (int q = 0; q < 4; q++) d[i][j][q] = 0.f;

    int a_row_in = (lane & 7) + ((lane >> 3) & 1) * 8;
    int a_kb_off = lane >> 4;
    int b_sub = lane >> 3;
    int b_row_in = lane & 7;

    for (int ch = 0; ch < NCHUNK; ch++) {
        int st = ch & (NSTAGE - 1);
        int rem = NCHUNK - 1 - ch;
        if (rem >= 2)      asm volatile("cp.async.wait_group 2;" ::: "memory");
        else if (rem == 1) asm volatile("cp.async.wait_group 1;" ::: "memory");
        else               asm volatile("cp.async.wait_group 0;" ::: "memory");
        __syncthreads();

        if (ch + 3 < NCHUNK)
            issue_chunk(sm, (ch + 3) & (NSTAGE - 1), ch + 3, m0, n0, tid);

        uint32_t sb = smem_u32(sm + st * SSZ);
        #pragma unroll
        for (int ks = 0; ks < 4; ks++) {
            uint32_t a[2][4], bf[4][2];
            #pragma unroll
            for (int mt = 0; mt < 2; mt++) {
                int row = warp_m + mt * 16 + a_row_in;
                int kb = 2 * ks + a_kb_off;
                uint32_t ad = sb + row * 128 + ((kb ^ (row & 7)) << 4);
                ldsm4(a[mt], ad);
            }
            #pragma unroll
            for (int q = 0; q < 2; q++) {
                int row = warp_n + (2 * q + (b_sub >> 1)) * 8 + b_row_in;
                int kb = 2 * ks + (b_sub & 1);
                uint32_t bd = sb + OFF_B + row * 128 + ((kb ^ (row & 7)) << 4);
                uint32_t r[4];
                ldsm4(r, bd);
                bf[2 * q][0] = r[0]; bf[2 * q][1] = r[1];
                bf[2 * q + 1][0] = r[2]; bf[2 * q + 1][1] = r[3];
            }
            #pragma unroll
            for (int mt = 0; mt < 2; mt++)
                #pragma unroll
                for (int nt = 0; nt < 4; nt++)
                    mma16816(d[mt][nt], a[mt], bf[nt]);
        }
    }

    int r4 = lane >> 2, c2 = (lane & 3) * 2;
    #pragma unroll
    for (int mt = 0; mt < 2; mt++) {
        int o0 = m0 + warp_m + mt * 16 + r4;
        int o1 = o0 + 8;
        float i0 = rsqrtf(var[o0] + 1e-5f) * gamma[o0];
        float i1 = rsqrtf(var[o1] + 1e-5f) * gamma[o1];
        float u0 = mean[o0], u1 = mean[o1];
        float t0 = beta[o0], t1 = beta[o1];
        #pragma unroll
        for (int nt = 0; nt < 4; nt++) {
            int col = n0 + warp_n + nt * 8 + c2;
            float2 v0, v1;
            v0.x = fmaxf((d[mt][nt][0] - u0) * i0 + t0, 0.f);
            v0.y = fmaxf((d[mt][nt][1] - u0) * i0 + t0, 0.f);
            v1.x = fmaxf((d[mt][nt][2] - u1) * i1 + t1, 0.f);
            v1.y = fmaxf((d[mt][nt][3] - u1) * i1 + t1, 0.f);
            *(float2*)(out + o0 * 1024 + col) = v0;
            *(float2*)(out + o1 * 1024 + col) = v1;
        }
    }
}

extern "C" void kernel_launch(void* const* d_in, const int* in_sizes, int n_in,
                              void* d_out, int out_size) {
    const float* x     = (const float*)d_in[0];
    const float* w1    = (const float*)d_in[1];
    const float* b1    = (const float*)d_in[2];
    const float* w2    = (const float*)d_in[3];
    const float* b2    = (const float*)d_in[4];
    const float* cw    = (const float*)d_in[5];
    const float* gamma = (const float*)d_in[6];
    const float* beta  = (const float*)d_in[7];
    const float* mean  = (const float*)d_in[8];
    const float* var   = (const float*)d_in[9];
    float* out = (float*)d_out;

    cudaFuncSetAttribute(k_gemm, cudaFuncAttributeMaxDynamicSharedMemorySize, NSTAGE * SSZ);

    k_prep<<<2049, 256>>>(cw, x);                         // 0
    k_se<<<32, 256>>>(w1, b1, w2, b2);                    // 1
    k_chan8<<<128, 512>>>(x);                             // 2
    k_attn<<<1024, 256>>>();                              // 3  <- profiled (clock canary: ~11us)
    k_gemm<<<dim3(16, 8), 256, NSTAGE * SSZ>>>(gamma, beta, mean, var, out);  // 4
}

// round 17
// speedup vs baseline: 1.6070x; 1.1553x over previous
#include <cuda_runtime.h>
#include <cuda_bf16.h>
#include <cuda_fp16.h>
#include <math.h>
#include <stdint.h>

#define HW 1024
#define CC 1024
#define CR 64

__device__ __forceinline__ float fsigmoid(float v) {
    return __fdividef(1.f, 1.f + __expf(-v));
}

// ---------------- scratch ----------------
__device__ float g_A[32 * 32];
__device__ float g_mean[CC];
__device__ float g_xrp[HW * CC];            // sigmoid(x_se), pixel-major [p][c]
__device__ __half g_W[1024 * 2048];         // conv weight, fp16
__device__ __half g_B[HW * 2048];           // GEMM B, fp16, K-major [p][k]

// ---------------- fused prep: convW fp16 | per-channel mean | gaussian table ------
__global__ void k_prep(const float* __restrict__ w, const float* __restrict__ x) {
    int b = blockIdx.x;
    int t = threadIdx.x;   // 256
    if (b < 1024) {
        int base = (b * 256 + t) * 8;
        float4 v0 = *(const float4*)(w + base);
        float4 v1 = *(const float4*)(w + base + 4);
        __half h[8];
        float vv[8] = {v0.x, v0.y, v0.z, v0.w, v1.x, v1.y, v1.z, v1.w};
        #pragma unroll
        for (int i = 0; i < 8; i++) h[i] = __float2half(vv[i]);
        *(uint4*)(g_W + base) = *(uint4*)h;
    } else if (b < 2048) {
        int c = b - 1024;
        const float* xc = x + c * HW;
        float s = 0.f;
        #pragma unroll
        for (int q = 0; q < 4; q++) s += xc[t + q * 256];
        #pragma unroll
        for (int o = 16; o > 0; o >>= 1) s += __shfl_xor_sync(0xffffffffu, s, o);
        __shared__ float red[8];
        int lane = t & 31, wv = t >> 5;
        if (lane == 0) red[wv] = s;
        __syncthreads();
        if (t == 0) {
            float tt = 0.f;
            #pragma unroll
            for (int i = 0; i < 8; i++) tt += red[i];
            g_mean[c] = tt * (1.0f / 1024.0f);
        }
    } else {
        // 1D gaussian table, row-normalized
        int i = t >> 3;
        int x0 = (t & 7) * 4;
        float e[4], s = 0.f;
        #pragma unroll
        for (int q = 0; q < 4; q++) {
            float d = (float)(i - (x0 + q));
            e[q] = __expf(-d * d / 4.5f);
            s += e[q];
        }
        s += __shfl_xor_sync(0xffffffffu, s, 1);
        s += __shfl_xor_sync(0xffffffffu, s, 2);
        s += __shfl_xor_sync(0xffffffffu, s, 4);
        float inv = __fdividef(1.f, s);
        #pragma unroll
        for (int q = 0; q < 4; q++) g_A[i * 32 + x0 + q] = e[q] * inv;
    }
}

// ---------------- fused SE + channel stage: 8 channels/block, 128 blocks, 512 thr --
// Each block redundantly computes the SE MLP (w1 is L2-resident), producing its
// 8 channels' scales, then: scale+sigmoid -> g_xrp, separable gaussian -> g_B spat.
__global__ void __launch_bounds__(512)
k_chan8(const float* __restrict__ x,
        const float* __restrict__ w1, const float* __restrict__ b1,
        const float* __restrict__ w2, const float* __restrict__ b2) {
    __shared__ float ym[CC];
    __shared__ float h1s[CR];
    __shared__ float scs[8];
    __shared__ float xs[8][1024];
    __shared__ float At[32][36];    // At[y][k] = A[k][y]
    __shared__ float tm[32][36];
    int c0 = blockIdx.x * 8;
    int t = threadIdx.x;            // 512
    int w = t >> 5, lane = t & 31;

    // ---- SE layer 1: 16 warps x 4 hidden units ----
    #pragma unroll
    for (int q = 0; q < 2; q++) ym[t + q * 512] = g_mean[t + q * 512];
    __syncthreads();
    #pragma unroll
    for (int jj = 0; jj < 4; jj++) {
        int j = w * 4 + jj;
        const float* wr = w1 + j * CC;
        float s = 0.f;
        #pragma unroll
        for (int k = 0; k < 32; k++) s += wr[lane + k * 32] * ym[lane + k * 32];
        #pragma unroll
        for (int o = 16; o > 0; o >>= 1) s += __shfl_xor_sync(0xffffffffu, s, o);
        if (lane == 0) h1s[j] = fmaxf(s + b1[j], 0.f);
    }
    __syncthreads();
    // ---- SE layer 2: warps 0..7 -> this block's 8 channels ----
    if (w < 8) {
        int c = c0 + w;
        const float* wr = w2 + c * CR;
        float s = wr[lane] * h1s[lane] + wr[lane + 32] * h1s[lane + 32];
        #pragma unroll
        for (int o = 16; o > 0; o >>= 1) s += __shfl_xor_sync(0xffffffffu, s, o);
        if (lane == 0) scs[w] = fsigmoid(s + b2[c]);
    }
    // ---- gaussian table ----
    if (t < 256) {
        #pragma unroll
        for (int q = 0; q < 4; q++) {
            int i = t + q * 256;    // i = k*32 + y
            At[i & 31][i >> 5] = g_A[i];
        }
    }
    __syncthreads();

    // ---- load + scale 8 channels ----
    #pragma unroll
    for (int i = 0; i < 8; i++) {
        float sc = scs[i];
        #pragma unroll
        for (int q = 0; q < 2; q++) {
            int p = t + q * 512;
            xs[i][p] = x[(c0 + i) * HW + p] * sc;
        }
    }
    __syncthreads();

    // ---- sigmoid -> xrp (pixel-major, 32B/pixel segments) ----
    #pragma unroll
    for (int q = 0; q < 2; q++) {
        int p = t + q * 512;
        float v[8];
        #pragma unroll
        for (int i = 0; i < 8; i++) v[i] = fsigmoid(xs[i][p]);
        *(float4*)(g_xrp + p * CC + c0)     = make_float4(v[0], v[1], v[2], v[3]);
        *(float4*)(g_xrp + p * CC + c0 + 4) = make_float4(v[4], v[5], v[6], v[7]);
    }

    // ---- separable gaussian per channel ----
    int xrow = t >> 4, k2 = (t & 15) * 2;
    #pragma unroll
    for (int i = 0; i < 8; i++) {
        float a0 = 0.f, a1 = 0.f;
        #pragma unroll
        for (int y = 0; y < 32; y++) {
            float xv = xs[i][xrow * 32 + y];
            a0 += xv * At[y][k2];
            a1 += xv * At[y][k2 + 1];
        }
        __syncthreads();
        tm[xrow][k2] = a0;
        tm[xrow][k2 + 1] = a1;
        __syncthreads();
        float o0 = 0.f, o1 = 0.f;
        #pragma unroll
        for (int xx = 0; xx < 32; xx++) {
            float av = At[xx][xrow];
            o0 += av * tm[xx][k2];
            o1 += av * tm[xx][k2 + 1];
        }
        __syncthreads();
        xs[i][xrow * 32 + k2] = o0;
        xs[i][xrow * 32 + k2 + 1] = o1;
    }
    __syncthreads();

    // ---- spat half of B: per pixel, 8 contiguous fp16 (one uint4) ----
    #pragma unroll
    for (int q = 0; q < 2; q++) {
        int p = t + q * 512;
        __half h[8];
        #pragma unroll
        for (int i = 0; i < 8; i++) h[i] = __float2half(xs[i][p]);
        *(uint4*)(g_B + p * 2048 + 1024 + c0) = *(uint4*)h;
    }
}

// ---------------- scrambled 3x3 softmax attention -> B (k<1024) ----------------
// snF[F] = neighbor_row[F%9][F/9] (stride-9 scatter fill, conflict-free). Linear
// addressing in hot loops + register cache sv[][] so pass 2 does zero LDS.
__global__ void k_attn() {
    __shared__ float snF[9216];     // [c*9 + kidx]
    __shared__ float wsum[8][9];
    __shared__ float lg[9];
    __shared__ float attn[9];
    int p = blockIdx.x;
    int py = p >> 5, px = p & 31;
    int t = threadIdx.x;  // 256

    #pragma unroll
    for (int kidx = 0; kidx < 9; kidx++) {
        int sy = py + kidx / 3 - 1;
        int sx = px + kidx % 3 - 1;
        bool valid = ((unsigned)sy < 32u) && ((unsigned)sx < 32u);
        const float* src = g_xrp + (sy * 32 + sx) * CC;
        #pragma unroll
        for (int q = 0; q < 4; q++) {
            int c = t + q * 256;
            snF[c * 9 + kidx] = valid ? src[c] : 0.f;
        }
    }
    __syncthreads();

    float pl[9];
    #pragma unroll
    for (int j = 0; j < 9; j++) pl[j] = 0.f;
    float sv[4][9];
    #pragma unroll
    for (int q = 0; q < 4; q++) {
        int cc = t + q * 256;
        float x1v = snF[cc * 9 + 4];           // center pixel = kidx 4
        #pragma unroll
        for (int j = 0; j < 9; j++) {
            float v = snF[j * 1024 + cc];      // snF[F], F = j*1024+cc
            sv[q][j] = v;
            pl[j] += x1v * v;
        }
    }
    int lane = t & 31, w = t >> 5;
    #pragma unroll
    for (int j = 0; j < 9; j++) {
        float s = pl[j];
        #pragma unroll
        for (int o = 16; o > 0; o >>= 1) s += __shfl_xor_sync(0xffffffffu, s, o);
        if (lane == 0) wsum[w][j] = s;
    }
    __syncthreads();
    if (t < 9) {
        float s = 0.f;
        #pragma unroll
        for (int i = 0; i < 8; i++) s += wsum[i][t];
        lg[t] = s;
    }
    __syncthreads();
    if (t == 0) {
        float m = lg[0];
        #pragma unroll
        for (int j = 1; j < 9; j++) m = fmaxf(m, lg[j]);
        float e[9], ss = 0.f;
        #pragma unroll
        for (int j = 0; j < 9; j++) { e[j] = __expf(lg[j] - m); ss += e[j]; }
        float inv = __fdividef(1.f, ss);
        #pragma unroll
        for (int j = 0; j < 9; j++) attn[j] = e[j] * inv;
    }
    __syncthreads();
    float at[9];
    #pragma unroll
    for (int j = 0; j < 9; j++) at[j] = attn[j];
    #pragma unroll
    for (int q = 0; q < 4; q++) {
        int cc = t + q * 256;
        float acc = 0.f;
        #pragma unroll
        for (int j = 0; j < 9; j++)
            acc += at[j] * sv[q][j];
        g_B[p * 2048 + cc] = __float2half(acc);
    }
}

// =========================== mma.sync fp16 single-term GEMM ===========================
// D[1024][1024] = W[1024][2048] @ B^T, W and B fp16.
// 8 MMAs per k16-step. CTA tile 128x64, K chunks of 64, 4-stage cp.async,
// issue-before-compute, single sync per iteration.
#define NCHUNK 32
#define NSTAGE 4
#define SSZ    24576   // A 16K | B 8K
#define OFF_B  16384

__device__ __forceinline__ uint32_t smem_u32(const void* p) {
    uint32_t a;
    asm("{ .reg .u64 t; cvta.to.shared.u64 t, %1; cvt.u32.u64 %0, t; }" : "=r"(a) : "l"(p));
    return a;
}
__device__ __forceinline__ void cp16(uint32_t dst, const void* src) {
    asm volatile("cp.async.ca.shared.global [%0], [%1], 16;" :: "r"(dst), "l"(src) : "memory");
}
__device__ __forceinline__ void ldsm4(uint32_t* r, uint32_t addr) {
    asm volatile("ldmatrix.sync.aligned.m8n8.x4.shared.b16 {%0,%1,%2,%3}, [%4];"
                 : "=r"(r[0]), "=r"(r[1]), "=r"(r[2]), "=r"(r[3]) : "r"(addr));
}
__device__ __forceinline__ void mma16816(float* d, const uint32_t* a, const uint32_t* b) {
    asm volatile(
        "mma.sync.aligned.m16n8k16.row.col.f32.f16.f16.f32 "
        "{%0,%1,%2,%3}, {%4,%5,%6,%7}, {%8,%9}, {%0,%1,%2,%3};"
        : "+f"(d[0]), "+f"(d[1]), "+f"(d[2]), "+f"(d[3])
        : "r"(a[0]), "r"(a[1]), "r"(a[2]), "r"(a[3]), "r"(b[0]), "r"(b[1]));
}

__device__ __forceinline__ void issue_chunk(char* smbase, int st, int ch,
                                            int m0, int n0, int tid) {
    uint32_t sb = smem_u32(smbase + st * SSZ);
    const char* ww = (const char*)g_W;
    const char* bb = (const char*)g_B;
    int kbyte = ch * 128;   // 64 fp16 = 128 bytes per chunk
    #pragma unroll
    for (int q = 0; q < 4; q++) {
        int idx = tid + q * 256;
        int row = idx >> 3, kb = idx & 7;
        int swz = row * 128 + ((kb ^ (row & 7)) << 4);
        long goff = (long)(m0 + row) * 4096 + kbyte + kb * 16;
        cp16(sb + swz, ww + goff);
    }
    #pragma unroll
    for (int q = 0; q < 2; q++) {
        int idx = tid + q * 256;
        int row = idx >> 3, kb = idx & 7;
        int swz = row * 128 + ((kb ^ (row & 7)) << 4);
        long goff = (long)(n0 + row) * 4096 + kbyte + kb * 16;
        cp16(sb + OFF_B + swz, bb + goff);
    }
    asm volatile("cp.async.commit_group;" ::: "memory");
}

__global__ void __launch_bounds__(256)
k_gemm(const float* __restrict__ gamma, const float* __restrict__ beta,
       const float* __restrict__ mean, const float* __restrict__ var,
       float* __restrict__ out) {
    extern __shared__ char sm[];
    int tid = threadIdx.x;
    int wid = tid >> 5, lane = tid & 31;
    int n0 = blockIdx.x * 64;
    int m0 = blockIdx.y * 128;
    int warp_m = (wid >> 1) * 32;
    int warp_n = (wid & 1) * 32;

    issue_chunk(sm, 0, 0, m0, n0, tid);
    issue_chunk(sm, 1, 1, m0, n0, tid);
    issue_chunk(sm, 2, 2, m0, n0, tid);

    float d[2][4][4];
    #pragma unroll
    for (int i = 0; i < 2; i++)
        #pragma unroll
        for (int j = 0; j < 4; j++)
            #pragma unroll
            for (int q = 0; q < 4; q++) d[i][j][q] = 0.f;

    int a_row_in = (lane & 7) + ((lane >> 3) & 1) * 8;
    int a_kb_off = lane >> 4;
    int b_sub = lane >> 3;
    int b_row_in = lane & 7;

    for (int ch = 0; ch < NCHUNK; ch++) {
        int st = ch & (NSTAGE - 1);
        int rem = NCHUNK - 1 - ch;
        if (rem >= 2)      asm volatile("cp.async.wait_group 2;" ::: "memory");
        else if (rem == 1) asm volatile("cp.async.wait_group 1;" ::: "memory");
        else               asm volatile("cp.async.wait_group 0;" ::: "memory");
        __syncthreads();

        if (ch + 3 < NCHUNK)
            issue_chunk(sm, (ch + 3) & (NSTAGE - 1), ch + 3, m0, n0, tid);

        uint32_t sb = smem_u32(sm + st * SSZ);
        #pragma unroll
        for (int ks = 0; ks < 4; ks++) {
            uint32_t a[2][4], bf[4][2];
            #pragma unroll
            for (int mt = 0; mt < 2; mt++) {
                int row = warp_m + mt * 16 + a_row_in;
                int kb = 2 * ks + a_kb_off;
                uint32_t ad = sb + row * 128 + ((kb ^ (row & 7)) << 4);
                ldsm4(a[mt], ad);
            }
            #pragma unroll
            for (int q = 0; q < 2; q++) {
                int row = warp_n + (2 * q + (b_sub >> 1)) * 8 + b_row_in;
                int kb = 2 * ks + (b_sub & 1);
                uint32_t bd = sb + OFF_B + row * 128 + ((kb ^ (row & 7)) << 4);
                uint32_t r[4];
                ldsm4(r, bd);
                bf[2 * q][0] = r[0]; bf[2 * q][1] = r[1];
                bf[2 * q + 1][0] = r[2]; bf[2 * q + 1][1] = r[3];
            }
            #pragma unroll
            for (int mt = 0; mt < 2; mt++)
                #pragma unroll
                for (int nt = 0; nt < 4; nt++)
                    mma16816(d[mt][nt], a[mt], bf[nt]);
        }
    }

    int r4 = lane >> 2, c2 = (lane & 3) * 2;
    #pragma unroll
    for (int mt = 0; mt < 2; mt++) {
        int o0 = m0 + warp_m + mt * 16 + r4;
        int o1 = o0 + 8;
        float i0 = rsqrtf(var[o0] + 1e-5f) * gamma[o0];
        float i1 = rsqrtf(var[o1] + 1e-5f) * gamma[o1];
        float u0 = mean[o0], u1 = mean[o1];
        float t0 = beta[o0], t1 = beta[o1];
        #pragma unroll
        for (int nt = 0; nt < 4; nt++) {
            int col = n0 + warp_n + nt * 8 + c2;
            float2 v0, v1;
            v0.x = fmaxf((d[mt][nt][0] - u0) * i0 + t0, 0.f);
            v0.y = fmaxf((d[mt][nt][1] - u0) * i0 + t0, 0.f);
            v1.x = fmaxf((d[mt][nt][2] - u1) * i1 + t1, 0.f);
            v1.y = fmaxf((d[mt][nt][3] - u1) * i1 + t1, 0.f);
            *(float2*)(out + o0 * 1024 + col) = v0;
            *(float2*)(out + o1 * 1024 + col) = v1;
        }
    }
}

extern "C" void kernel_launch(void* const* d_in, const int* in_sizes, int n_in,
                              void* d_out, int out_size) {
    const float* x     = (const float*)d_in[0];
    const float* w1    = (const float*)d_in[1];
    const float* b1    = (const float*)d_in[2];
    const float* w2    = (const float*)d_in[3];
    const float* b2    = (const float*)d_in[4];
    const float* cw    = (const float*)d_in[5];
    const float* gamma = (const float*)d_in[6];
    const float* beta  = (const float*)d_in[7];
    const float* mean  = (const float*)d_in[8];
    const float* var   = (const float*)d_in[9];
    float* out = (float*)d_out;

    cudaFuncSetAttribute(k_gemm, cudaFuncAttributeMaxDynamicSharedMemorySize, NSTAGE * SSZ);

    k_prep<<<2049, 256>>>(cw, x);                         // 0
    k_chan8<<<128, 512>>>(x, w1, b1, w2, b2);             // 1 (SE fused in)
    k_attn<<<1024, 256>>>();                              // 2
    k_gemm<<<dim3(16, 8), 256, NSTAGE * SSZ>>>(gamma, beta, mean, var, out);  // 3 <- profiled
}